// round 12
// baseline (speedup 1.0000x reference)
#include <cuda_runtime.h>
#include <cuda_fp16.h>
#include <cstdint>

// ---------------------------------------------------------------------------
// Problem dims
// ---------------------------------------------------------------------------
#define HW        128
#define OW        126
#define LIN       15876              // (128-2)^2
#define K_TILE    64
#define N_KTILES  252                // LIN_PAD = 16128
#define LIN_PAD   (N_KTILES * K_TILE)
#define TRI       8256
#define BATCH     64
#define NDIM      128
#define M_TILE    256
#define N_MTILES  33                 // 33*256 = 8448
#define T_PAD     8448
#define KSPLIT    4
#define TILES_PER_SPLIT (N_KTILES / KSPLIT)   // 63

// SMEM layout, pitch 144 B (conflict-free ldmatrix).
// A stage: 256 x 144 = 36864 (fp16), x2;  B stage: 64 x 144 = 9216 (fp16), x3
#define A_PITCH   144
#define A_STG     36864u
#define A_OFF(s)  ((uint32_t)(s) * A_STG)
#define B_BASE    73728u
#define B_STG     9216u
#define B_OFF(st) (B_BASE + (uint32_t)(st) * B_STG)
#define SMEM_BYTES 101376

// ---------------------------------------------------------------------------
// Scratch (device globals — no allocation allowed)
// ---------------------------------------------------------------------------
__device__ __half g_hb[(size_t)BATCH * LIN_PAD];   // [b][l] fp16 h
__device__ float  g_vp[(size_t)KSPLIT * BATCH * T_PAD];

// ---------------------------------------------------------------------------
// helpers
// ---------------------------------------------------------------------------
__device__ __forceinline__ uint32_t smem_u32(const void* p) {
    uint32_t a;
    asm("{ .reg .u64 t; cvta.to.shared.u64 t, %1; cvt.u32.u64 %0, t; }"
        : "=r"(a) : "l"(p));
    return a;
}

__device__ __forceinline__ void cp_async16(uint32_t dst, const void* src) {
    asm volatile("cp.async.cg.shared.global [%0], [%1], 16;"
                 :: "r"(dst), "l"(src) : "memory");
}
__device__ __forceinline__ void cp_commit() {
    asm volatile("cp.async.commit_group;" ::: "memory");
}
template <int N>
__device__ __forceinline__ void cp_wait() {
    asm volatile("cp.async.wait_group %0;" :: "n"(N) : "memory");
}

__device__ __forceinline__ void ldsm4(uint32_t& r0, uint32_t& r1,
                                      uint32_t& r2, uint32_t& r3, uint32_t addr) {
    asm volatile("ldmatrix.sync.aligned.m8n8.x4.shared.b16 {%0,%1,%2,%3}, [%4];"
                 : "=r"(r0), "=r"(r1), "=r"(r2), "=r"(r3) : "r"(addr));
}

__device__ __forceinline__ void mma_f16(float* c,
                                        uint32_t a0, uint32_t a1, uint32_t a2, uint32_t a3,
                                        uint32_t b0, uint32_t b1) {
    asm volatile(
        "mma.sync.aligned.m16n8k16.row.col.f32.f16.f16.f32 "
        "{%0,%1,%2,%3}, {%4,%5,%6,%7}, {%8,%9}, {%0,%1,%2,%3};"
        : "+f"(c[0]), "+f"(c[1]), "+f"(c[2]), "+f"(c[3])
        : "r"(a0), "r"(a1), "r"(a2), "r"(a3), "r"(b0), "r"(b1));
}

__device__ __forceinline__ uint32_t pack_h2(float x, float y) {
    __half2 h = __floats2half2_rn(x, y);
    return *reinterpret_cast<uint32_t*>(&h);
}

// ---------------------------------------------------------------------------
// Kernel 1: fused conv -> fp16 h, [b][l] layout (pad rows zero)
// ---------------------------------------------------------------------------
__global__ void conv_fuse_kernel(const float* __restrict__ x,
                                 const float* __restrict__ w1,
                                 const float* __restrict__ b1,
                                 const float* __restrict__ w2,
                                 const float* __restrict__ b2) {
    int idx = blockIdx.x * blockDim.x + threadIdx.x;
    int b = idx / LIN_PAD;
    int l = idx - b * LIN_PAD;

    float val = 0.0f;
    if (l < LIN) {
        int i = l / OW;
        int j = l - i * OW;
        const float* xp = x + (size_t)b * (HW * HW) + i * HW + j;
        float acc = b2[0];
        #pragma unroll
        for (int c = 0; c < 4; c++) {
            float s = b1[c];
            #pragma unroll
            for (int di = 0; di < 3; di++)
                #pragma unroll
                for (int dj = 0; dj < 3; dj++)
                    s = fmaf(xp[di * HW + dj], w1[c * 9 + di * 3 + dj], s);
            acc = fmaf(w2[c], fmaxf(s, 0.0f), acc);
        }
        val = acc;
    }
    g_hb[idx] = __float2half(val);
}

// ---------------------------------------------------------------------------
// GEMM helpers. 512 threads: arow = tid>>1 (0..255), aq = tid&1.
// Each thread: 8 float4 of W -> fp16 at LDG time -> 8 uint2 (32 k-vals).
// ---------------------------------------------------------------------------
__device__ __forceinline__ void ldg_a_cvt(const float* __restrict__ W,
                                          int t, int l0, int aq, bool trow_ok,
                                          uint2 (&a)[8]) {
    #pragma unroll
    for (int j = 0; j < 8; j++) {
        int l = l0 + (aq * 8 + j) * 4;
        float4 w = make_float4(0.f, 0.f, 0.f, 0.f);
        if (trow_ok && l < LIN)
            w = *reinterpret_cast<const float4*>(W + (size_t)t * LIN + l);
        a[j] = make_uint2(pack_h2(w.x, w.y), pack_h2(w.z, w.w));
    }
}

__device__ __forceinline__ void sts_a(char* smem, int stage, int row, int aq,
                                      const uint2 (&a)[8]) {
    uint32_t base = A_OFF(stage) + (uint32_t)row * A_PITCH + (uint32_t)aq * 64;
    #pragma unroll
    for (int j = 0; j < 8; j++)
        *reinterpret_cast<uint2*>(smem + base + (uint32_t)j * 8) = a[j];
}

// B tile: 64 rows x 128 B = 512 chunks, one per thread
__device__ __forceinline__ void cpasync_b(uint32_t sb, int st, int ktg, int tid) {
    int row = tid >> 3;
    int ch  = tid & 7;
    uint32_t dst = sb + B_OFF(st) + (uint32_t)row * A_PITCH + (uint32_t)ch * 16;
    cp_async16(dst, g_hb + (size_t)row * LIN_PAD + ktg * K_TILE + ch * 8);
}

// warp tile 32(m) x 32(n): per kstep 2 A-ldsm + 2 B-ldsm + 8 MMA
__device__ __forceinline__ void compute_tile(uint32_t sb, int stage, int bst,
                                             int wm, int wn, int lid,
                                             float (&acc)[2][4][4]) {
    const uint32_t lrow = (uint32_t)(lid & 15);
    const uint32_t lhi  = (uint32_t)((lid >> 4) << 4);

    uint32_t aH0 = sb + A_OFF(stage) + (wm * 32 + lrow) * A_PITCH + lhi;
    uint32_t aH1 = aH0 + 16 * A_PITCH;
    uint32_t bH0 = sb + B_OFF(bst) + (wn * 32 + lrow) * A_PITCH + lhi;
    uint32_t bH1 = bH0 + 16 * A_PITCH;

    #pragma unroll
    for (int ks = 0; ks < 4; ks++) {
        const uint32_t ko = (uint32_t)ks * 32;   // 16 fp16 = 32 B per kstep

        uint32_t a0[4], a1[4];
        ldsm4(a0[0], a0[1], a0[2], a0[3], aH0 + ko);
        ldsm4(a1[0], a1[1], a1[2], a1[3], aH1 + ko);

        uint32_t b0, b1, b2, b3, c0, c1, c2, c3;
        ldsm4(b0, b1, b2, b3, bH0 + ko);         // (b0,b2)=n0-7, (b1,b3)=n8-15
        ldsm4(c0, c1, c2, c3, bH1 + ko);         // n16-23, n24-31

        mma_f16(acc[0][0], a0[0], a0[1], a0[2], a0[3], b0, b2);
        mma_f16(acc[0][1], a0[0], a0[1], a0[2], a0[3], b1, b3);
        mma_f16(acc[0][2], a0[0], a0[1], a0[2], a0[3], c0, c2);
        mma_f16(acc[0][3], a0[0], a0[1], a0[2], a0[3], c1, c3);
        mma_f16(acc[1][0], a1[0], a1[1], a1[2], a1[3], b0, b2);
        mma_f16(acc[1][1], a1[0], a1[1], a1[2], a1[3], b1, b3);
        mma_f16(acc[1][2], a1[0], a1[1], a1[2], a1[3], c0, c2);
        mma_f16(acc[1][3], a1[0], a1[1], a1[2], a1[3], c1, c3);
    }
}

// ---------------------------------------------------------------------------
// Kernel 2: fp16 HMMA GEMM, CTA tile 256x64, 132 CTAs x 512 threads (16 warps)
// 8x2 warp grid (warp tile 32x32). A double-buffered, B triple-buffered.
// ---------------------------------------------------------------------------
__global__ __launch_bounds__(512, 1)
void gemm_tc_kernel(const float* __restrict__ W) {
    extern __shared__ char smem[];
    const uint32_t sb = smem_u32(smem);

    const int tid = threadIdx.x;
    const int wid = tid >> 5;
    const int lid = tid & 31;
    const int g   = lid >> 2;
    const int t4  = lid & 3;
    const int wm  = wid & 7;        // 8 row groups x 32
    const int wn  = wid >> 3;       // 2 col groups x 32

    const int mtile = blockIdx.x >> 2;
    const int split = blockIdx.x & 3;
    const int t0    = mtile * M_TILE;
    const int kt0   = split * TILES_PER_SPLIT;

    const int arow  = tid >> 1;
    const int aq    = tid & 1;
    const int atrow = t0 + arow;
    const bool trow_ok = (atrow < TRI);

    float acc[2][4][4];
    #pragma unroll
    for (int i = 0; i < 2; i++)
        #pragma unroll
        for (int j = 0; j < 4; j++)
            #pragma unroll
            for (int k = 0; k < 4; k++)
                acc[i][j][k] = 0.f;

    uint2 aR[8];

    // ---- prologue ----
    cpasync_b(sb, 0, kt0 + 0, tid);
    cp_commit();
    cpasync_b(sb, 1, kt0 + 1, tid);
    cp_commit();
    ldg_a_cvt(W, atrow, (kt0 + 0) * K_TILE, aq, trow_ok, aR);
    sts_a(smem, 0, arow, aq, aR);
    ldg_a_cvt(W, atrow, (kt0 + 1) * K_TILE, aq, trow_ok, aR);
    cp_wait<1>();
    __syncthreads();

    int bs = 0;
    for (int kt = 0; kt < TILES_PER_SPLIT; kt++) {
        const int nxt_bs = (bs + 2 >= 3) ? bs - 1 : bs + 2;

        if (kt + 2 < TILES_PER_SPLIT) {
            cpasync_b(sb, nxt_bs, kt0 + kt + 2, tid);
            cp_commit();
        }
        if (kt + 1 < TILES_PER_SPLIT)
            sts_a(smem, (kt + 1) & 1, arow, aq, aR);
        if (kt + 2 < TILES_PER_SPLIT)
            ldg_a_cvt(W, atrow, (kt0 + kt + 2) * K_TILE, aq, trow_ok, aR);

        compute_tile(sb, kt & 1, bs, wm, wn, lid, acc);

        if (kt + 2 < TILES_PER_SPLIT)      cp_wait<1>();
        else if (kt + 1 < TILES_PER_SPLIT) cp_wait<0>();
        __syncthreads();

        bs = (bs + 1 >= 3) ? 0 : bs + 1;
    }

    // ---- epilogue ----
    float* vp = g_vp + (size_t)split * BATCH * T_PAD;
    #pragma unroll
    for (int mt = 0; mt < 2; mt++) {
        #pragma unroll
        for (int nt = 0; nt < 4; nt++) {
            int r  = t0 + wm * 32 + mt * 16 + g;
            int cb = wn * 32 + nt * 8 + 2 * t4;
            vp[(size_t)cb       * T_PAD + r]     = acc[mt][nt][0];
            vp[(size_t)(cb + 1) * T_PAD + r]     = acc[mt][nt][1];
            vp[(size_t)cb       * T_PAD + r + 8] = acc[mt][nt][2];
            vp[(size_t)(cb + 1) * T_PAD + r + 8] = acc[mt][nt][3];
        }
    }
}

// ---------------------------------------------------------------------------
// Kernel 3: symmetric triu scatter + split-K(4) reduce + bias
// ---------------------------------------------------------------------------
__global__ void scatter_kernel(float* __restrict__ out,
                               const float* __restrict__ bias) {
    int idx = blockIdx.x * blockDim.x + threadIdx.x;
    if (idx >= BATCH * NDIM * NDIM) return;
    int b = idx >> 14;
    int r = (idx >> 7) & 127;
    int c = idx & 127;
    int i = min(r, c);
    int j = max(r, c);
    int t = i * NDIM - (i * (i - 1)) / 2 + (j - i);
    float v = bias[t];
    #pragma unroll
    for (int s = 0; s < KSPLIT; s++)
        v += g_vp[((size_t)s * BATCH + b) * T_PAD + t];
    out[idx] = v;
}

// ---------------------------------------------------------------------------
extern "C" void kernel_launch(void* const* d_in, const int* in_sizes, int n_in,
                              void* d_out, int out_size) {
    const float* x       = (const float*)d_in[0];
    const float* conv1_w = (const float*)d_in[1];
    const float* conv1_b = (const float*)d_in[2];
    const float* conv2_w = (const float*)d_in[3];
    const float* conv2_b = (const float*)d_in[4];
    const float* out_w   = (const float*)d_in[5];
    const float* out_b   = (const float*)d_in[6];
    float* out = (float*)d_out;

    cudaFuncSetAttribute(gemm_tc_kernel,
                         cudaFuncAttributeMaxDynamicSharedMemorySize, SMEM_BYTES);

    conv_fuse_kernel<<<(BATCH * LIN_PAD) / 256, 256>>>(x, conv1_w, conv1_b,
                                                       conv2_w, conv2_b);
    gemm_tc_kernel<<<N_MTILES * KSPLIT, 512, SMEM_BYTES>>>(out_w);
    scatter_kernel<<<(BATCH * NDIM * NDIM + 255) / 256, 256>>>(out, out_b);
}

// round 13
// speedup vs baseline: 1.0300x; 1.0300x over previous
#include <cuda_runtime.h>
#include <cuda_fp16.h>
#include <cstdint>

// ---------------------------------------------------------------------------
// Problem dims
// ---------------------------------------------------------------------------
#define HW        128
#define OW        126
#define LIN       15876              // (128-2)^2
#define K_TILE    128
#define N_KTILES  126                // LIN_PAD = 16128
#define LIN_PAD   (N_KTILES * K_TILE)
#define TRI       8256
#define BATCH     64
#define NDIM      128
#define T_PAD     8320               // 65*128
#define N_MTILES  65
#define KSPLIT    2
#define TILES_PER_SPLIT (N_KTILES / KSPLIT)   // 63

// SMEM layout, pitch 272 B (odd multiple of 16B -> conflict-free ldmatrix).
// A stage: 128 x 272 = 34816 (fp16), x2;  B stage: 64 x 272 = 17408 (fp16), x3
#define A_PITCH   272
#define A_STG     34816u
#define A_OFF(s)  ((uint32_t)(s) * A_STG)
#define B_BASE    69632u
#define B_STG     17408u
#define B_OFF(st) (B_BASE + (uint32_t)(st) * B_STG)
#define SMEM_BYTES 121856            // 119 KB -> 1 CTA/SM

// ---------------------------------------------------------------------------
// Scratch (device globals — no allocation allowed)
// ---------------------------------------------------------------------------
__device__ __half g_hb[(size_t)BATCH * LIN_PAD];   // [b][l] fp16 h
__device__ float  g_vp[(size_t)KSPLIT * BATCH * T_PAD];

// ---------------------------------------------------------------------------
// helpers
// ---------------------------------------------------------------------------
__device__ __forceinline__ uint32_t smem_u32(const void* p) {
    uint32_t a;
    asm("{ .reg .u64 t; cvta.to.shared.u64 t, %1; cvt.u32.u64 %0, t; }"
        : "=r"(a) : "l"(p));
    return a;
}

__device__ __forceinline__ void cp_async16(uint32_t dst, const void* src) {
    asm volatile("cp.async.cg.shared.global [%0], [%1], 16;"
                 :: "r"(dst), "l"(src) : "memory");
}
__device__ __forceinline__ void cp_commit() {
    asm volatile("cp.async.commit_group;" ::: "memory");
}
template <int N>
__device__ __forceinline__ void cp_wait() {
    asm volatile("cp.async.wait_group %0;" :: "n"(N) : "memory");
}

__device__ __forceinline__ void ldsm4(uint32_t* r, uint32_t addr) {
    asm volatile("ldmatrix.sync.aligned.m8n8.x4.shared.b16 {%0,%1,%2,%3}, [%4];"
                 : "=r"(r[0]), "=r"(r[1]), "=r"(r[2]), "=r"(r[3]) : "r"(addr));
}

__device__ __forceinline__ void mma_f16(float* c,
                                        uint32_t a0, uint32_t a1, uint32_t a2, uint32_t a3,
                                        uint32_t b0, uint32_t b1) {
    asm volatile(
        "mma.sync.aligned.m16n8k16.row.col.f32.f16.f16.f32 "
        "{%0,%1,%2,%3}, {%4,%5,%6,%7}, {%8,%9}, {%0,%1,%2,%3};"
        : "+f"(c[0]), "+f"(c[1]), "+f"(c[2]), "+f"(c[3])
        : "r"(a0), "r"(a1), "r"(a2), "r"(a3), "r"(b0), "r"(b1));
}

__device__ __forceinline__ uint32_t pack_h2(float x, float y) {
    __half2 h = __floats2half2_rn(x, y);
    return *reinterpret_cast<uint32_t*>(&h);
}

// ---------------------------------------------------------------------------
// Kernel 1: fused conv -> fp16 h, [b][l] layout (pad region zero)
// ---------------------------------------------------------------------------
__global__ void conv_fuse_kernel(const float* __restrict__ x,
                                 const float* __restrict__ w1,
                                 const float* __restrict__ b1,
                                 const float* __restrict__ w2,
                                 const float* __restrict__ b2) {
    int idx = blockIdx.x * blockDim.x + threadIdx.x;
    int b = idx / LIN_PAD;
    int l = idx - b * LIN_PAD;

    float val = 0.0f;
    if (l < LIN) {
        int i = l / OW;
        int j = l - i * OW;
        const float* xp = x + (size_t)b * (HW * HW) + i * HW + j;
        float acc = b2[0];
        #pragma unroll
        for (int c = 0; c < 4; c++) {
            float s = b1[c];
            #pragma unroll
            for (int di = 0; di < 3; di++)
                #pragma unroll
                for (int dj = 0; dj < 3; dj++)
                    s = fmaf(xp[di * HW + dj], w1[c * 9 + di * 3 + dj], s);
            acc = fmaf(w2[c], fmaxf(s, 0.0f), acc);
        }
        val = acc;
    }
    g_hb[idx] = __float2half(val);
}

// ---------------------------------------------------------------------------
// GEMM helpers. 512 threads: arow = tid>>2 (0..127), aq = tid&3.
// Each thread covers 32 floats (64 B) of the 512-B W row per K-tile.
// ---------------------------------------------------------------------------
__device__ __forceinline__ void ldg_a(const float* __restrict__ W,
                                      int t, int l0, int aq, bool trow_ok,
                                      float4 (&a)[8]) {
    #pragma unroll
    for (int j = 0; j < 8; j++) {
        int l = l0 + aq * 32 + j * 4;
        if (trow_ok && l < LIN)
            a[j] = *reinterpret_cast<const float4*>(W + (size_t)t * LIN + l);
        else
            a[j] = make_float4(0.f, 0.f, 0.f, 0.f);
    }
}

__device__ __forceinline__ void sts_a(char* smem, int stage, int row, int aq,
                                      const float4 (&a)[8]) {
    uint32_t base = A_OFF(stage) + (uint32_t)row * A_PITCH + (uint32_t)aq * 64;
    #pragma unroll
    for (int j = 0; j < 8; j++) {
        *reinterpret_cast<uint2*>(smem + base + (uint32_t)j * 8) =
            make_uint2(pack_h2(a[j].x, a[j].y), pack_h2(a[j].z, a[j].w));
    }
}

// B tile: 64 rows x 256 B = 1024 chunks, two per thread
__device__ __forceinline__ void cpasync_b(uint32_t sb, int st, int ktg, int tid) {
    #pragma unroll
    for (int i = 0; i < 2; i++) {
        int cid = tid + 512 * i;
        int row = cid >> 4;
        int ch  = cid & 15;
        uint32_t dst = sb + B_OFF(st) + (uint32_t)row * A_PITCH + (uint32_t)ch * 16;
        cp_async16(dst, g_hb + (size_t)row * LIN_PAD + ktg * K_TILE + ch * 8);
    }
}

// warp tile 32(m) x 16(n), 8 ksteps, fragment prefetch one kstep ahead
__device__ __forceinline__ void compute_tile(uint32_t sb, int stage, int bst,
                                             int wm, int wn, int lid,
                                             float (&acc)[2][2][4]) {
    const uint32_t lrow = (uint32_t)(lid & 15);
    const uint32_t lhi  = (uint32_t)((lid >> 4) << 4);

    uint32_t aH0 = sb + A_OFF(stage) + (wm * 32 + lrow) * A_PITCH + lhi;
    uint32_t aH1 = aH0 + 16 * A_PITCH;
    uint32_t bH  = sb + B_OFF(bst) + (wn * 16 + lrow) * A_PITCH + lhi;

    uint32_t a0[2][4], a1[2][4], bb[2][4];

    ldsm4(a0[0], aH0);
    ldsm4(a1[0], aH1);
    ldsm4(bb[0], bH);

    #pragma unroll
    for (int ks = 0; ks < 8; ks++) {
        const int cur = ks & 1;
        const int nxt = cur ^ 1;
        if (ks < 7) {
            const uint32_t ko = (uint32_t)(ks + 1) * 32;
            ldsm4(a0[nxt], aH0 + ko);
            ldsm4(a1[nxt], aH1 + ko);
            ldsm4(bb[nxt], bH + ko);
        }
        // (bb[cur][0], bb[cur][2]) = n0-7, (bb[cur][1], bb[cur][3]) = n8-15
        mma_f16(acc[0][0], a0[cur][0], a0[cur][1], a0[cur][2], a0[cur][3],
                bb[cur][0], bb[cur][2]);
        mma_f16(acc[0][1], a0[cur][0], a0[cur][1], a0[cur][2], a0[cur][3],
                bb[cur][1], bb[cur][3]);
        mma_f16(acc[1][0], a1[cur][0], a1[cur][1], a1[cur][2], a1[cur][3],
                bb[cur][0], bb[cur][2]);
        mma_f16(acc[1][1], a1[cur][0], a1[cur][1], a1[cur][2], a1[cur][3],
                bb[cur][1], bb[cur][3]);
    }
}

// ---------------------------------------------------------------------------
// Kernel 2: fp16 HMMA GEMM, 130 CTAs x 512 threads (16 warps, 4x4 grid)
// K_TILE=128. A double-buffered, B triple-buffered, one barrier per tile.
// ---------------------------------------------------------------------------
__global__ __launch_bounds__(512, 1)
void gemm_tc_kernel(const float* __restrict__ W) {
    extern __shared__ char smem[];
    const uint32_t sb = smem_u32(smem);

    const int tid = threadIdx.x;
    const int wid = tid >> 5;
    const int lid = tid & 31;
    const int g   = lid >> 2;
    const int t4  = lid & 3;
    const int wm  = wid & 3;        // 4 row groups x 32
    const int wn  = wid >> 2;       // 4 col groups x 16

    const int mtile = blockIdx.x >> 1;
    const int split = blockIdx.x & 1;
    const int t0    = mtile * 128;
    const int kt0   = split * TILES_PER_SPLIT;

    const int arow  = tid >> 2;
    const int aq    = tid & 3;
    const int atrow = t0 + arow;
    const bool trow_ok = (atrow < TRI);

    float acc[2][2][4];
    #pragma unroll
    for (int i = 0; i < 2; i++)
        #pragma unroll
        for (int j = 0; j < 2; j++)
            #pragma unroll
            for (int k = 0; k < 4; k++)
                acc[i][j][k] = 0.f;

    float4 aR[8];

    // ---- prologue ----
    cpasync_b(sb, 0, kt0 + 0, tid);
    cp_commit();
    cpasync_b(sb, 1, kt0 + 1, tid);
    cp_commit();
    ldg_a(W, atrow, (kt0 + 0) * K_TILE, aq, trow_ok, aR);
    sts_a(smem, 0, arow, aq, aR);
    ldg_a(W, atrow, (kt0 + 1) * K_TILE, aq, trow_ok, aR);
    cp_wait<1>();
    __syncthreads();

    int bs = 0;
    for (int kt = 0; kt < TILES_PER_SPLIT; kt++) {
        const int nxt_bs = (bs + 2 >= 3) ? bs - 1 : bs + 2;

        if (kt + 2 < TILES_PER_SPLIT) {
            cpasync_b(sb, nxt_bs, kt0 + kt + 2, tid);
            cp_commit();
        }
        if (kt + 1 < TILES_PER_SPLIT)
            sts_a(smem, (kt + 1) & 1, arow, aq, aR);
        if (kt + 2 < TILES_PER_SPLIT)
            ldg_a(W, atrow, (kt0 + kt + 2) * K_TILE, aq, trow_ok, aR);

        compute_tile(sb, kt & 1, bs, wm, wn, lid, acc);

        if (kt + 2 < TILES_PER_SPLIT)      cp_wait<1>();
        else if (kt + 1 < TILES_PER_SPLIT) cp_wait<0>();
        __syncthreads();

        bs = (bs + 1 >= 3) ? 0 : bs + 1;
    }

    // ---- epilogue ----
    float* vp = g_vp + (size_t)split * BATCH * T_PAD;
    #pragma unroll
    for (int mt = 0; mt < 2; mt++) {
        #pragma unroll
        for (int nt = 0; nt < 2; nt++) {
            int r  = t0 + wm * 32 + mt * 16 + g;
            int cb = wn * 16 + nt * 8 + 2 * t4;
            vp[(size_t)cb       * T_PAD + r]     = acc[mt][nt][0];
            vp[(size_t)(cb + 1) * T_PAD + r]     = acc[mt][nt][1];
            vp[(size_t)cb       * T_PAD + r + 8] = acc[mt][nt][2];
            vp[(size_t)(cb + 1) * T_PAD + r + 8] = acc[mt][nt][3];
        }
    }
}

// ---------------------------------------------------------------------------
// Kernel 3: symmetric triu scatter + split-K reduce + bias
// ---------------------------------------------------------------------------
__global__ void scatter_kernel(float* __restrict__ out,
                               const float* __restrict__ bias) {
    int idx = blockIdx.x * blockDim.x + threadIdx.x;
    if (idx >= BATCH * NDIM * NDIM) return;
    int b = idx >> 14;
    int r = (idx >> 7) & 127;
    int c = idx & 127;
    int i = min(r, c);
    int j = max(r, c);
    int t = i * NDIM - (i * (i - 1)) / 2 + (j - i);
    out[idx] = g_vp[(size_t)b * T_PAD + t] +
               g_vp[(size_t)(BATCH + b) * T_PAD + t] + bias[t];
}

// ---------------------------------------------------------------------------
extern "C" void kernel_launch(void* const* d_in, const int* in_sizes, int n_in,
                              void* d_out, int out_size) {
    const float* x       = (const float*)d_in[0];
    const float* conv1_w = (const float*)d_in[1];
    const float* conv1_b = (const float*)d_in[2];
    const float* conv2_w = (const float*)d_in[3];
    const float* conv2_b = (const float*)d_in[4];
    const float* out_w   = (const float*)d_in[5];
    const float* out_b   = (const float*)d_in[6];
    float* out = (float*)d_out;

    cudaFuncSetAttribute(gemm_tc_kernel,
                         cudaFuncAttributeMaxDynamicSharedMemorySize, SMEM_BYTES);

    conv_fuse_kernel<<<(BATCH * LIN_PAD) / 256, 256>>>(x, conv1_w, conv1_b,
                                                       conv2_w, conv2_b);
    gemm_tc_kernel<<<N_MTILES * KSPLIT, 512, SMEM_BYTES>>>(out_w);
    scatter_kernel<<<(BATCH * NDIM * NDIM + 255) / 256, 256>>>(out, out_b);
}

// round 14
// speedup vs baseline: 1.4312x; 1.3895x over previous
#include <cuda_runtime.h>
#include <cuda_fp16.h>
#include <cstdint>

// ---------------------------------------------------------------------------
// Problem dims
// ---------------------------------------------------------------------------
#define HW        128
#define OW        126
#define LIN       15876              // (128-2)^2
#define K_TILE    64
#define N_KTILES  252                // LIN_PAD = 16128
#define LIN_PAD   (N_KTILES * K_TILE)
#define TRI       8256
#define BATCH     64
#define NDIM      128
#define T_PAD     8320               // 65*128
#define N_MTILES  65
#define KSPLIT    2
#define TILES_PER_SPLIT (N_KTILES / KSPLIT)   // 126

// SMEM layout, pitch 144 B (conflict-free ldmatrix, proven in R6/R10).
// A stage: 128 x 144 = 18432 (fp16), x2;  B stage: 64 x 144 = 9216 (fp16), x3
#define A_PITCH   144
#define A_STG     18432u
#define A_OFF(s)  ((uint32_t)(s) * A_STG)
#define B_BASE    36864u
#define B_STG     9216u
#define B_OFF(st) (B_BASE + (uint32_t)(st) * B_STG)
#define SMEM_BYTES 64512

// ---------------------------------------------------------------------------
// Scratch (device globals — no allocation allowed)
// ---------------------------------------------------------------------------
__device__ __half g_hb[(size_t)BATCH * LIN_PAD];   // [b][l] fp16 h
__device__ float  g_vp[(size_t)KSPLIT * BATCH * T_PAD];

// ---------------------------------------------------------------------------
// helpers
// ---------------------------------------------------------------------------
__device__ __forceinline__ uint32_t smem_u32(const void* p) {
    uint32_t a;
    asm("{ .reg .u64 t; cvta.to.shared.u64 t, %1; cvt.u32.u64 %0, t; }"
        : "=r"(a) : "l"(p));
    return a;
}

__device__ __forceinline__ void cp_async16(uint32_t dst, const void* src) {
    asm volatile("cp.async.cg.shared.global [%0], [%1], 16;"
                 :: "r"(dst), "l"(src) : "memory");
}
__device__ __forceinline__ void cp_commit() {
    asm volatile("cp.async.commit_group;" ::: "memory");
}
template <int N>
__device__ __forceinline__ void cp_wait() {
    asm volatile("cp.async.wait_group %0;" :: "n"(N) : "memory");
}

__device__ __forceinline__ void ldsm4(uint32_t* r, uint32_t addr) {
    asm volatile("ldmatrix.sync.aligned.m8n8.x4.shared.b16 {%0,%1,%2,%3}, [%4];"
                 : "=r"(r[0]), "=r"(r[1]), "=r"(r[2]), "=r"(r[3]) : "r"(addr));
}

__device__ __forceinline__ void mma_f16(float* c,
                                        uint32_t a0, uint32_t a1, uint32_t a2, uint32_t a3,
                                        uint32_t b0, uint32_t b1) {
    asm volatile(
        "mma.sync.aligned.m16n8k16.row.col.f32.f16.f16.f32 "
        "{%0,%1,%2,%3}, {%4,%5,%6,%7}, {%8,%9}, {%0,%1,%2,%3};"
        : "+f"(c[0]), "+f"(c[1]), "+f"(c[2]), "+f"(c[3])
        : "r"(a0), "r"(a1), "r"(a2), "r"(a3), "r"(b0), "r"(b1));
}

__device__ __forceinline__ uint32_t pack_h2(float x, float y) {
    __half2 h = __floats2half2_rn(x, y);
    return *reinterpret_cast<uint32_t*>(&h);
}

// ---------------------------------------------------------------------------
// Kernel 1: fused conv -> fp16 h, [b][l] layout (pad region zero)
// ---------------------------------------------------------------------------
__global__ void conv_fuse_kernel(const float* __restrict__ x,
                                 const float* __restrict__ w1,
                                 const float* __restrict__ b1,
                                 const float* __restrict__ w2,
                                 const float* __restrict__ b2) {
    int idx = blockIdx.x * blockDim.x + threadIdx.x;
    int b = idx / LIN_PAD;
    int l = idx - b * LIN_PAD;

    float val = 0.0f;
    if (l < LIN) {
        int i = l / OW;
        int j = l - i * OW;
        const float* xp = x + (size_t)b * (HW * HW) + i * HW + j;
        float acc = b2[0];
        #pragma unroll
        for (int c = 0; c < 4; c++) {
            float s = b1[c];
            #pragma unroll
            for (int di = 0; di < 3; di++)
                #pragma unroll
                for (int dj = 0; dj < 3; dj++)
                    s = fmaf(xp[di * HW + dj], w1[c * 9 + di * 3 + dj], s);
            acc = fmaf(w2[c], fmaxf(s, 0.0f), acc);
        }
        val = acc;
    }
    g_hb[idx] = __float2half(val);
}

// ---------------------------------------------------------------------------
// GEMM helpers (512 threads: arow = tid>>2, aq = tid&3) — R10 mapping
// ---------------------------------------------------------------------------
__device__ __forceinline__ void ldg_a(const float* __restrict__ W,
                                      int t, int l0, int aq, bool trow_ok,
                                      float4 (&a)[4]) {
    #pragma unroll
    for (int j = 0; j < 4; j++) {
        int l = l0 + (aq * 4 + j) * 4;
        if (trow_ok && l < LIN)
            a[j] = *reinterpret_cast<const float4*>(W + (size_t)t * LIN + l);
        else
            a[j] = make_float4(0.f, 0.f, 0.f, 0.f);
    }
}

// convert + store: 2x STS.128 per thread (was 4x STS.64)
__device__ __forceinline__ void sts_a(char* smem, int stage, int row, int aq,
                                      const float4 (&a)[4]) {
    uint32_t base = A_OFF(stage) + (uint32_t)row * A_PITCH + (uint32_t)aq * 32;
    *reinterpret_cast<uint4*>(smem + base) =
        make_uint4(pack_h2(a[0].x, a[0].y), pack_h2(a[0].z, a[0].w),
                   pack_h2(a[1].x, a[1].y), pack_h2(a[1].z, a[1].w));
    *reinterpret_cast<uint4*>(smem + base + 16) =
        make_uint4(pack_h2(a[2].x, a[2].y), pack_h2(a[2].z, a[2].w),
                   pack_h2(a[3].x, a[3].y), pack_h2(a[3].z, a[3].w));
}

// B tile: 64 rows x 128 B = 512 chunks, one cp.async per thread
__device__ __forceinline__ void cpasync_b(uint32_t sb, int st, int ktg, int tid) {
    int row = tid >> 3;                          // batch 0..63
    int ch  = tid & 7;                           // 16B chunk
    uint32_t dst = sb + B_OFF(st) + (uint32_t)row * A_PITCH + (uint32_t)ch * 16;
    cp_async16(dst, g_hb + (size_t)row * LIN_PAD + ktg * K_TILE + ch * 8);
}

// warp tile 32(m) x 16(n): 4 ksteps, fragments double-buffered (prefetch +1)
__device__ __forceinline__ void compute_tile(uint32_t sb, int stage, int bst,
                                             int wm, int wn, int lid,
                                             float (&acc)[2][2][4]) {
    const uint32_t lrow = (uint32_t)(lid & 15);
    const uint32_t lhi  = (uint32_t)((lid >> 4) << 4);

    uint32_t aH0 = sb + A_OFF(stage) + (wm * 32 + lrow) * A_PITCH + lhi;
    uint32_t aH1 = aH0 + 16 * A_PITCH;
    uint32_t bH  = sb + B_OFF(bst) + (wn * 16 + lrow) * A_PITCH + lhi;

    uint32_t a0[2][4], a1[2][4], bb[2][4];
    ldsm4(a0[0], aH0);
    ldsm4(a1[0], aH1);
    ldsm4(bb[0], bH);

    #pragma unroll
    for (int ks = 0; ks < 4; ks++) {
        const int cur = ks & 1;
        const int nxt = cur ^ 1;
        if (ks < 3) {
            const uint32_t ko = (uint32_t)(ks + 1) * 32;
            ldsm4(a0[nxt], aH0 + ko);
            ldsm4(a1[nxt], aH1 + ko);
            ldsm4(bb[nxt], bH + ko);
        }
        // (bb[cur][0], bb[cur][2]) = n0-7, (bb[cur][1], bb[cur][3]) = n8-15
        mma_f16(acc[0][0], a0[cur][0], a0[cur][1], a0[cur][2], a0[cur][3],
                bb[cur][0], bb[cur][2]);
        mma_f16(acc[0][1], a0[cur][0], a0[cur][1], a0[cur][2], a0[cur][3],
                bb[cur][1], bb[cur][3]);
        mma_f16(acc[1][0], a1[cur][0], a1[cur][1], a1[cur][2], a1[cur][3],
                bb[cur][0], bb[cur][2]);
        mma_f16(acc[1][1], a1[cur][0], a1[cur][1], a1[cur][2], a1[cur][3],
                bb[cur][1], bb[cur][3]);
    }
}

// ---------------------------------------------------------------------------
// Kernel 2: fp16 HMMA GEMM, 130 CTAs x 512 threads (16 warps, 4x4 grid)
// A double-buffered, B triple-buffered, one barrier per tile. (R10 + micro)
// ---------------------------------------------------------------------------
__global__ __launch_bounds__(512, 1)
void gemm_tc_kernel(const float* __restrict__ W) {
    extern __shared__ char smem[];
    const uint32_t sb = smem_u32(smem);

    const int tid = threadIdx.x;
    const int wid = tid >> 5;
    const int lid = tid & 31;
    const int g   = lid >> 2;
    const int t4  = lid & 3;
    const int wm  = wid & 3;        // 4 row groups x 32
    const int wn  = wid >> 2;       // 4 col groups x 16

    const int mtile = blockIdx.x >> 1;
    const int split = blockIdx.x & 1;
    const int t0    = mtile * 128;
    const int kt0   = split * TILES_PER_SPLIT;

    const int arow  = tid >> 2;
    const int aq    = tid & 3;
    const int atrow = t0 + arow;
    const bool trow_ok = (atrow < TRI);

    float acc[2][2][4];
    #pragma unroll
    for (int i = 0; i < 2; i++)
        #pragma unroll
        for (int j = 0; j < 2; j++)
            #pragma unroll
            for (int k = 0; k < 4; k++)
                acc[i][j][k] = 0.f;

    float4 aR[4];

    // ---- prologue ----
    cpasync_b(sb, 0, kt0 + 0, tid);
    cp_commit();
    cpasync_b(sb, 1, kt0 + 1, tid);
    cp_commit();
    ldg_a(W, atrow, (kt0 + 0) * K_TILE, aq, trow_ok, aR);
    sts_a(smem, 0, arow, aq, aR);
    ldg_a(W, atrow, (kt0 + 1) * K_TILE, aq, trow_ok, aR);
    cp_wait<1>();
    __syncthreads();

    int bs = 0;
    for (int kt = 0; kt < TILES_PER_SPLIT; kt++) {
        const int nxt_bs = (bs + 2 >= 3) ? bs - 1 : bs + 2;

        if (kt + 2 < TILES_PER_SPLIT) {
            cpasync_b(sb, nxt_bs, kt0 + kt + 2, tid);
            cp_commit();
        }
        if (kt + 1 < TILES_PER_SPLIT)
            sts_a(smem, (kt + 1) & 1, arow, aq, aR);
        if (kt + 2 < TILES_PER_SPLIT)
            ldg_a(W, atrow, (kt0 + kt + 2) * K_TILE, aq, trow_ok, aR);

        compute_tile(sb, kt & 1, bs, wm, wn, lid, acc);

        if (kt + 2 < TILES_PER_SPLIT)      cp_wait<1>();
        else if (kt + 1 < TILES_PER_SPLIT) cp_wait<0>();
        __syncthreads();

        bs = (bs + 1 >= 3) ? 0 : bs + 1;
    }

    // ---- epilogue ----
    float* vp = g_vp + (size_t)split * BATCH * T_PAD;
    #pragma unroll
    for (int mt = 0; mt < 2; mt++) {
        #pragma unroll
        for (int nt = 0; nt < 2; nt++) {
            int r  = t0 + wm * 32 + mt * 16 + g;
            int cb = wn * 16 + nt * 8 + 2 * t4;
            vp[(size_t)cb       * T_PAD + r]     = acc[mt][nt][0];
            vp[(size_t)(cb + 1) * T_PAD + r]     = acc[mt][nt][1];
            vp[(size_t)cb       * T_PAD + r + 8] = acc[mt][nt][2];
            vp[(size_t)(cb + 1) * T_PAD + r + 8] = acc[mt][nt][3];
        }
    }
}

// ---------------------------------------------------------------------------
// Kernel 3: symmetric triu scatter + split-K reduce + bias
// ---------------------------------------------------------------------------
__global__ void scatter_kernel(float* __restrict__ out,
                               const float* __restrict__ bias) {
    int idx = blockIdx.x * blockDim.x + threadIdx.x;
    if (idx >= BATCH * NDIM * NDIM) return;
    int b = idx >> 14;
    int r = (idx >> 7) & 127;
    int c = idx & 127;
    int i = min(r, c);
    int j = max(r, c);
    int t = i * NDIM - (i * (i - 1)) / 2 + (j - i);
    out[idx] = g_vp[(size_t)b * T_PAD + t] +
               g_vp[(size_t)(BATCH + b) * T_PAD + t] + bias[t];
}

// ---------------------------------------------------------------------------
extern "C" void kernel_launch(void* const* d_in, const int* in_sizes, int n_in,
                              void* d_out, int out_size) {
    const float* x       = (const float*)d_in[0];
    const float* conv1_w = (const float*)d_in[1];
    const float* conv1_b = (const float*)d_in[2];
    const float* conv2_w = (const float*)d_in[3];
    const float* conv2_b = (const float*)d_in[4];
    const float* out_w   = (const float*)d_in[5];
    const float* out_b   = (const float*)d_in[6];
    float* out = (float*)d_out;

    cudaFuncSetAttribute(gemm_tc_kernel,
                         cudaFuncAttributeMaxDynamicSharedMemorySize, SMEM_BYTES);

    conv_fuse_kernel<<<(BATCH * LIN_PAD) / 256, 256>>>(x, conv1_w, conv1_b,
                                                       conv2_w, conv2_b);
    gemm_tc_kernel<<<N_MTILES * KSPLIT, 512, SMEM_BYTES>>>(out_w);
    scatter_kernel<<<(BATCH * NDIM * NDIM + 255) / 256, 256>>>(out, out_b);
}

// round 15
// speedup vs baseline: 1.5656x; 1.0940x over previous
#include <cuda_runtime.h>
#include <cuda_fp16.h>
#include <cstdint>

// ---------------------------------------------------------------------------
// Problem dims
// ---------------------------------------------------------------------------
#define HW        128
#define OW        126
#define LIN       15876              // (128-2)^2
#define K_TILE    64
#define N_KTILES  252                // LIN_PAD = 16128
#define LIN_PAD   (N_KTILES * K_TILE)
#define TRI       8256
#define BATCH     64
#define NDIM      128
#define T_PAD     8320               // 65*128
#define N_MTILES  65
#define NCTA      152                // GB300: 152 SMs, 1 CTA/SM (reg-limited)
#define TOTAL_UNITS (N_MTILES * N_KTILES)   // 16380
#define NSLOTS    4

// SMEM layout, pitch 144 B (conflict-free ldmatrix).
// A stage: 128 x 144 = 18432 (fp16), x2;  B stage: 64 x 144 = 9216 (fp16), x3
#define A_PITCH   144
#define A_STG     18432u
#define A_OFF(s)  ((uint32_t)(s) * A_STG)
#define B_BASE    36864u
#define B_STG     9216u
#define B_OFF(st) (B_BASE + (uint32_t)(st) * B_STG)
#define SMEM_BYTES 64512

// ---------------------------------------------------------------------------
// Scratch (device globals — no allocation allowed)
// g_vp: 4 slots; slots never written stay zero (module-load zero-init),
// written regions are rewritten identically every launch -> deterministic.
// ---------------------------------------------------------------------------
__device__ __half g_hb[(size_t)BATCH * LIN_PAD];   // [b][l] fp16 h
__device__ float  g_vp[(size_t)NSLOTS * BATCH * T_PAD];

// ---------------------------------------------------------------------------
// helpers
// ---------------------------------------------------------------------------
__device__ __forceinline__ uint32_t smem_u32(const void* p) {
    uint32_t a;
    asm("{ .reg .u64 t; cvta.to.shared.u64 t, %1; cvt.u32.u64 %0, t; }"
        : "=r"(a) : "l"(p));
    return a;
}

__device__ __forceinline__ void cp_async16(uint32_t dst, const void* src) {
    asm volatile("cp.async.cg.shared.global [%0], [%1], 16;"
                 :: "r"(dst), "l"(src) : "memory");
}
__device__ __forceinline__ void cp_commit() {
    asm volatile("cp.async.commit_group;" ::: "memory");
}
template <int N>
__device__ __forceinline__ void cp_wait() {
    asm volatile("cp.async.wait_group %0;" :: "n"(N) : "memory");
}

__device__ __forceinline__ void ldsm4(uint32_t* r, uint32_t addr) {
    asm volatile("ldmatrix.sync.aligned.m8n8.x4.shared.b16 {%0,%1,%2,%3}, [%4];"
                 : "=r"(r[0]), "=r"(r[1]), "=r"(r[2]), "=r"(r[3]) : "r"(addr));
}

__device__ __forceinline__ void mma_f16(float* c,
                                        uint32_t a0, uint32_t a1, uint32_t a2, uint32_t a3,
                                        uint32_t b0, uint32_t b1) {
    asm volatile(
        "mma.sync.aligned.m16n8k16.row.col.f32.f16.f16.f32 "
        "{%0,%1,%2,%3}, {%4,%5,%6,%7}, {%8,%9}, {%0,%1,%2,%3};"
        : "+f"(c[0]), "+f"(c[1]), "+f"(c[2]), "+f"(c[3])
        : "r"(a0), "r"(a1), "r"(a2), "r"(a3), "r"(b0), "r"(b1));
}

__device__ __forceinline__ uint32_t pack_h2(float x, float y) {
    __half2 h = __floats2half2_rn(x, y);
    return *reinterpret_cast<uint32_t*>(&h);
}

// unit-space partition: CTA j owns units [start_u(j), start_u(j+1))
__device__ __forceinline__ int start_u(int j) {
    return (int)(((long long)j * TOTAL_UNITS) / NCTA);
}

// ---------------------------------------------------------------------------
// Kernel 1: fused conv -> fp16 h, [b][l] layout (pad region zero)
// ---------------------------------------------------------------------------
__global__ void conv_fuse_kernel(const float* __restrict__ x,
                                 const float* __restrict__ w1,
                                 const float* __restrict__ b1,
                                 const float* __restrict__ w2,
                                 const float* __restrict__ b2) {
    int idx = blockIdx.x * blockDim.x + threadIdx.x;
    int b = idx / LIN_PAD;
    int l = idx - b * LIN_PAD;

    float val = 0.0f;
    if (l < LIN) {
        int i = l / OW;
        int j = l - i * OW;
        const float* xp = x + (size_t)b * (HW * HW) + i * HW + j;
        float acc = b2[0];
        #pragma unroll
        for (int c = 0; c < 4; c++) {
            float s = b1[c];
            #pragma unroll
            for (int di = 0; di < 3; di++)
                #pragma unroll
                for (int dj = 0; dj < 3; dj++)
                    s = fmaf(xp[di * HW + dj], w1[c * 9 + di * 3 + dj], s);
            acc = fmaf(w2[c], fmaxf(s, 0.0f), acc);
        }
        val = acc;
    }
    g_hb[idx] = __float2half(val);
}

// ---------------------------------------------------------------------------
// GEMM helpers (512 threads: arow = tid>>2, aq = tid&3)
// ---------------------------------------------------------------------------
__device__ __forceinline__ void ldg_a(const float* __restrict__ W,
                                      int t, int l0, int aq, bool trow_ok,
                                      float4 (&a)[4]) {
    #pragma unroll
    for (int j = 0; j < 4; j++) {
        int l = l0 + (aq * 4 + j) * 4;
        if (trow_ok && l < LIN)
            a[j] = *reinterpret_cast<const float4*>(W + (size_t)t * LIN + l);
        else
            a[j] = make_float4(0.f, 0.f, 0.f, 0.f);
    }
}

__device__ __forceinline__ void sts_a(char* smem, int stage, int row, int aq,
                                      const float4 (&a)[4]) {
    uint32_t base = A_OFF(stage) + (uint32_t)row * A_PITCH + (uint32_t)aq * 32;
    *reinterpret_cast<uint4*>(smem + base) =
        make_uint4(pack_h2(a[0].x, a[0].y), pack_h2(a[0].z, a[0].w),
                   pack_h2(a[1].x, a[1].y), pack_h2(a[1].z, a[1].w));
    *reinterpret_cast<uint4*>(smem + base + 16) =
        make_uint4(pack_h2(a[2].x, a[2].y), pack_h2(a[2].z, a[2].w),
                   pack_h2(a[3].x, a[3].y), pack_h2(a[3].z, a[3].w));
}

// B tile: 64 rows x 128 B = 512 chunks, one cp.async per thread
__device__ __forceinline__ void cpasync_b(uint32_t sb, int st, int ktg, int tid) {
    int row = tid >> 3;
    int ch  = tid & 7;
    uint32_t dst = sb + B_OFF(st) + (uint32_t)row * A_PITCH + (uint32_t)ch * 16;
    cp_async16(dst, g_hb + (size_t)row * LIN_PAD + ktg * K_TILE + ch * 8);
}

// warp tile 32(m) x 16(n): 4 ksteps, fragment double-buffer (prefetch +1)
__device__ __forceinline__ void compute_tile(uint32_t sb, int stage, int bst,
                                             int wm, int wn, int lid,
                                             float (&acc)[2][2][4]) {
    const uint32_t lrow = (uint32_t)(lid & 15);
    const uint32_t lhi  = (uint32_t)((lid >> 4) << 4);

    uint32_t aH0 = sb + A_OFF(stage) + (wm * 32 + lrow) * A_PITCH + lhi;
    uint32_t aH1 = aH0 + 16 * A_PITCH;
    uint32_t bH  = sb + B_OFF(bst) + (wn * 16 + lrow) * A_PITCH + lhi;

    uint32_t a0[2][4], a1[2][4], bb[2][4];
    ldsm4(a0[0], aH0);
    ldsm4(a1[0], aH1);
    ldsm4(bb[0], bH);

    #pragma unroll
    for (int ks = 0; ks < 4; ks++) {
        const int cur = ks & 1;
        const int nxt = cur ^ 1;
        if (ks < 3) {
            const uint32_t ko = (uint32_t)(ks + 1) * 32;
            ldsm4(a0[nxt], aH0 + ko);
            ldsm4(a1[nxt], aH1 + ko);
            ldsm4(bb[nxt], bH + ko);
        }
        mma_f16(acc[0][0], a0[cur][0], a0[cur][1], a0[cur][2], a0[cur][3],
                bb[cur][0], bb[cur][2]);
        mma_f16(acc[0][1], a0[cur][0], a0[cur][1], a0[cur][2], a0[cur][3],
                bb[cur][1], bb[cur][3]);
        mma_f16(acc[1][0], a1[cur][0], a1[cur][1], a1[cur][2], a1[cur][3],
                bb[cur][0], bb[cur][2]);
        mma_f16(acc[1][1], a1[cur][0], a1[cur][1], a1[cur][2], a1[cur][3],
                bb[cur][1], bb[cur][3]);
    }
}

// one pipelined segment: M-tile `mtile`, K-tiles [kt0, kt0+n_kt), -> slot
__device__ __forceinline__ void gemm_segment(const float* __restrict__ W,
                                             char* smem, uint32_t sb,
                                             int mtile, int kt0, int n_kt,
                                             int slot,
                                             int tid, int wid, int lid,
                                             int wm, int wn, int g, int t4) {
    const int t0    = mtile * 128;
    const int arow  = tid >> 2;
    const int aq    = tid & 3;
    const int atrow = t0 + arow;
    const bool trow_ok = (atrow < TRI);

    float acc[2][2][4];
    #pragma unroll
    for (int i = 0; i < 2; i++)
        #pragma unroll
        for (int j = 0; j < 2; j++)
            #pragma unroll
            for (int k = 0; k < 4; k++)
                acc[i][j][k] = 0.f;

    float4 aR[4];

    // ---- prologue (guarded for n_kt == 1) ----
    cpasync_b(sb, 0, kt0 + 0, tid);
    cp_commit();
    if (n_kt > 1) cpasync_b(sb, 1, kt0 + 1, tid);
    cp_commit();
    ldg_a(W, atrow, (kt0 + 0) * K_TILE, aq, trow_ok, aR);
    sts_a(smem, 0, arow, aq, aR);
    if (n_kt > 1) ldg_a(W, atrow, (kt0 + 1) * K_TILE, aq, trow_ok, aR);
    cp_wait<1>();
    __syncthreads();

    int bs = 0;
    for (int kt = 0; kt < n_kt; kt++) {
        const int nxt_bs = (bs + 2 >= 3) ? bs - 1 : bs + 2;

        if (kt + 2 < n_kt) {
            cpasync_b(sb, nxt_bs, kt0 + kt + 2, tid);
            cp_commit();
        }
        if (kt + 1 < n_kt)
            sts_a(smem, (kt + 1) & 1, arow, aq, aR);
        if (kt + 2 < n_kt)
            ldg_a(W, atrow, (kt0 + kt + 2) * K_TILE, aq, trow_ok, aR);

        compute_tile(sb, kt & 1, bs, wm, wn, lid, acc);

        if (kt + 2 < n_kt)      cp_wait<1>();
        else if (kt + 1 < n_kt) cp_wait<0>();
        __syncthreads();

        bs = (bs + 1 >= 3) ? 0 : bs + 1;
    }

    // ---- epilogue to slot ----
    float* vp = g_vp + (size_t)slot * BATCH * T_PAD;
    #pragma unroll
    for (int mt = 0; mt < 2; mt++) {
        #pragma unroll
        for (int nt = 0; nt < 2; nt++) {
            int r  = t0 + wm * 32 + mt * 16 + g;
            int cb = wn * 16 + nt * 8 + 2 * t4;
            vp[(size_t)cb       * T_PAD + r]     = acc[mt][nt][0];
            vp[(size_t)(cb + 1) * T_PAD + r]     = acc[mt][nt][1];
            vp[(size_t)cb       * T_PAD + r + 8] = acc[mt][nt][2];
            vp[(size_t)(cb + 1) * T_PAD + r + 8] = acc[mt][nt][3];
        }
    }
}

// ---------------------------------------------------------------------------
// Kernel 2: fp16 HMMA GEMM, 152 persistent CTAs x 512 threads (16 warps)
// Balanced flat (mtile, ktile) unit decomposition; <=2 segments per CTA.
// ---------------------------------------------------------------------------
__global__ __launch_bounds__(512, 1)
void gemm_tc_kernel(const float* __restrict__ W) {
    extern __shared__ char smem[];
    const uint32_t sb = smem_u32(smem);

    const int tid = threadIdx.x;
    const int wid = tid >> 5;
    const int lid = tid & 31;
    const int g   = lid >> 2;
    const int t4  = lid & 3;
    const int wm  = wid & 3;        // 4 row groups x 32
    const int wn  = wid >> 2;       // 4 col groups x 16

    const int cta   = blockIdx.x;
    int u     = start_u(cta);
    const int u_end = start_u(cta + 1);

    while (u < u_end) {
        const int m        = u / N_KTILES;
        const int tile_end = (m + 1) * N_KTILES;
        const int seg_end  = (u_end < tile_end) ? u_end : tile_end;
        const int kt0      = u - m * N_KTILES;
        const int n_kt     = seg_end - u;

        // slot = cta - (first CTA whose range contains unit m*N_KTILES)
        const int u0 = m * N_KTILES;
        int j0 = (int)(((long long)u0 * NCTA) / TOTAL_UNITS);
        while (start_u(j0 + 1) <= u0) j0++;
        while (start_u(j0) > u0) j0--;
        const int slot = cta - j0;

        gemm_segment(W, smem, sb, m, kt0, n_kt, slot,
                     tid, wid, lid, wm, wn, g, t4);

        u = seg_end;
        if (u < u_end) __syncthreads();   // smem handoff between segments
    }
}

// ---------------------------------------------------------------------------
// Kernel 3: symmetric triu scatter + 4-slot reduce + bias
// ---------------------------------------------------------------------------
__global__ void scatter_kernel(float* __restrict__ out,
                               const float* __restrict__ bias) {
    int idx = blockIdx.x * blockDim.x + threadIdx.x;
    if (idx >= BATCH * NDIM * NDIM) return;
    int b = idx >> 14;
    int r = (idx >> 7) & 127;
    int c = idx & 127;
    int i = min(r, c);
    int j = max(r, c);
    int t = i * NDIM - (i * (i - 1)) / 2 + (j - i);
    float v = bias[t];
    #pragma unroll
    for (int s = 0; s < NSLOTS; s++)
        v += g_vp[((size_t)s * BATCH + b) * T_PAD + t];
    out[idx] = v;
}

// ---------------------------------------------------------------------------
extern "C" void kernel_launch(void* const* d_in, const int* in_sizes, int n_in,
                              void* d_out, int out_size) {
    const float* x       = (const float*)d_in[0];
    const float* conv1_w = (const float*)d_in[1];
    const float* conv1_b = (const float*)d_in[2];
    const float* conv2_w = (const float*)d_in[3];
    const float* conv2_b = (const float*)d_in[4];
    const float* out_w   = (const float*)d_in[5];
    const float* out_b   = (const float*)d_in[6];
    float* out = (float*)d_out;

    cudaFuncSetAttribute(gemm_tc_kernel,
                         cudaFuncAttributeMaxDynamicSharedMemorySize, SMEM_BYTES);

    conv_fuse_kernel<<<(BATCH * LIN_PAD) / 256, 256>>>(x, conv1_w, conv1_b,
                                                       conv2_w, conv2_b);
    gemm_tc_kernel<<<NCTA, 512, SMEM_BYTES>>>(out_w);
    scatter_kernel<<<(BATCH * NDIM * NDIM + 255) / 256, 256>>>(out, out_b);
}